// round 1
// baseline (speedup 1.0000x reference)
#include <cuda_runtime.h>
#include <cuda_bf16.h>
#include <cstdint>

// ---------------------------------------------------------------------------
// Problem constants
//   x        [16, 3, 512, 512]
//   conv1_w  [16, 3, 3, 3]   + bn1 (16)
//   conv2_w  [32, 16, 3, 3]  + bn2 (32)
//   pf_w[32], pf_b[1], vocab_w[80,32], vocab_b[80], cls_w[80,80], cls_b[80]
//   out      [16, 80] fp32
// ---------------------------------------------------------------------------

#define BN_EPS 1e-5f

// ---- device scratch (no cudaMalloc allowed) -------------------------------
__device__ float              g_pool[16 * 16 * 256 * 256];  // pooled feature map
__device__ unsigned char      g_mask[256 * 256];
__device__ int                g_count_i;
__device__ float              g_S[16 * 32];                 // masked channel sums
__device__ unsigned long long g_w1p[27 * 16];               // folded conv1 w, packed {w,w}
__device__ unsigned long long g_w2p[144 * 32];              // folded conv2 w, packed {w,w}
__device__ float              g_bias1[16];
__device__ float              g_bias2[32];

// ---- f32x2 helpers (Blackwell packed fp32) --------------------------------
__device__ __forceinline__ unsigned long long pk2(float a, float b) {
    unsigned long long r;
    asm("mov.b64 %0, {%1, %2};" : "=l"(r) : "f"(a), "f"(b));
    return r;
}
__device__ __forceinline__ void upk2(unsigned long long v, float& a, float& b) {
    asm("mov.b64 {%0, %1}, %2;" : "=f"(a), "=f"(b) : "l"(v));
}
__device__ __forceinline__ unsigned long long f2fma(unsigned long long a,
                                                    unsigned long long b,
                                                    unsigned long long c) {
    unsigned long long d;
    asm("fma.rn.f32x2 %0, %1, %2, %3;" : "=l"(d) : "l"(a), "l"(b), "l"(c));
    return d;
}

// ---------------------------------------------------------------------------
// prep: fold BN into weights (duplicated into both f32x2 lanes), zero accums
// ---------------------------------------------------------------------------
__global__ void prep_kernel(const float* __restrict__ w1,
                            const float* __restrict__ g1, const float* __restrict__ b1,
                            const float* __restrict__ m1, const float* __restrict__ v1,
                            const float* __restrict__ w2,
                            const float* __restrict__ g2, const float* __restrict__ b2,
                            const float* __restrict__ m2, const float* __restrict__ v2) {
    int t = threadIdx.x;  // 256
    for (int i = t; i < 512; i += 256) g_S[i] = 0.f;
    if (t == 0) g_count_i = 0;
    for (int i = t; i < 16 * 27; i += 256) {
        int co = i / 27, k = i % 27;
        float s = g1[co] * rsqrtf(v1[co] + BN_EPS);
        float w = w1[co * 27 + k] * s;
        g_w1p[k * 16 + co] = pk2(w, w);
    }
    for (int i = t; i < 32 * 144; i += 256) {
        int co = i / 144, k = i % 144;
        float s = g2[co] * rsqrtf(v2[co] + BN_EPS);
        float w = w2[co * 144 + k] * s;
        g_w2p[k * 32 + co] = pk2(w, w);
    }
    if (t < 16) {
        float s = g1[t] * rsqrtf(v1[t] + BN_EPS);
        g_bias1[t] = b1[t] - m1[t] * s;
    }
    if (t < 32) {
        float s = g2[t] * rsqrtf(v2[t] + BN_EPS);
        g_bias2[t] = b2[t] - m2[t] * s;
    }
}

// ---------------------------------------------------------------------------
// K1: conv1(3->16, 3x3, pad1) + BN + ReLU + maxpool2x2, fused.
// Block = 16x16 pooled pixels (= 32x32 conv pixels), 256 threads,
// thread = one pooled pixel, all 16 channels, x-pairs packed in f32x2.
// ---------------------------------------------------------------------------
__global__ __launch_bounds__(256) void k1_kernel(const float* __restrict__ x) {
    __shared__ float              s_x[3 * 34 * 36];   // halo tile, row stride 36
    __shared__ unsigned long long s_w[27 * 16];
    __shared__ float              s_b[16];

    int b = blockIdx.z, bx = blockIdx.x, by = blockIdx.y;
    int tid = threadIdx.x;

    for (int i = tid; i < 27 * 16; i += 256) s_w[i] = g_w1p[i];
    if (tid < 16) s_b[tid] = g_bias1[tid];

    int y0 = by * 32 - 1, x0 = bx * 32 - 1;
    for (int i = tid; i < 3 * 34 * 34; i += 256) {
        int cin = i / 1156, rem = i % 1156, r = rem / 34, c = rem % 34;
        int gy = y0 + r, gx = x0 + c;
        float v = 0.f;
        if ((unsigned)gy < 512u && (unsigned)gx < 512u)
            v = x[((b * 3 + cin) * 512 + gy) * 512 + gx];
        s_x[cin * 1224 + r * 36 + c] = v;
    }
    __syncthreads();

    int tx = tid & 15, ty = tid >> 4;
    unsigned long long a0[16], a1[16];  // conv rows 0/1 of the 2x2 window, x-pair packed
#pragma unroll
    for (int i = 0; i < 16; i++) { a0[i] = 0ull; a1[i] = 0ull; }

#pragma unroll
    for (int cin = 0; cin < 3; cin++) {
        float rv[4][4];
        const float* base = s_x + cin * 1224 + (2 * ty) * 36 + 2 * tx;
#pragma unroll
        for (int r = 0; r < 4; r++) {
            float2 q0 = *(const float2*)(base + r * 36);
            float2 q1 = *(const float2*)(base + r * 36 + 2);
            rv[r][0] = q0.x; rv[r][1] = q0.y; rv[r][2] = q1.x; rv[r][3] = q1.y;
        }
#pragma unroll
        for (int ky = 0; ky < 3; ky++) {
#pragma unroll
            for (int kx = 0; kx < 3; kx++) {
                unsigned long long i0 = pk2(rv[ky][kx],     rv[ky][kx + 1]);
                unsigned long long i1 = pk2(rv[ky + 1][kx], rv[ky + 1][kx + 1]);
                int k = cin * 9 + ky * 3 + kx;
                const ulonglong2* wv = (const ulonglong2*)(s_w + k * 16);
#pragma unroll
                for (int c2 = 0; c2 < 8; c2++) {
                    ulonglong2 w = wv[c2];
                    a0[2 * c2]     = f2fma(i0, w.x, a0[2 * c2]);
                    a1[2 * c2]     = f2fma(i1, w.x, a1[2 * c2]);
                    a0[2 * c2 + 1] = f2fma(i0, w.y, a0[2 * c2 + 1]);
                    a1[2 * c2 + 1] = f2fma(i1, w.y, a1[2 * c2 + 1]);
                }
            }
        }
    }

    int py = by * 16 + ty, px = bx * 16 + tx;
#pragma unroll
    for (int co = 0; co < 16; co++) {
        float p0, p1, p2, p3;
        upk2(a0[co], p0, p1);
        upk2(a1[co], p2, p3);
        // relu(v+b) then max == relu(max(v)+b) (monotone)
        float m = fmaxf(fmaxf(p0, p1), fmaxf(p2, p3)) + s_b[co];
        m = fmaxf(m, 0.f);
        g_pool[((b * 16 + co) * 256 + py) * 256 + px] = m;
    }
}

// ---------------------------------------------------------------------------
// K2: conv2(16->32, 3x3, pad1) + BN + ReLU, never materialized.
// MODE 0: batch 0 only -> proposal-filter mask + count.
// MODE 1: all batches  -> masked channel sums S[b][c].
// Block tile = 64x8 pixels; 256 threads = 128 spatial (4 px each, two f32x2
// pairs) x 2 channel-groups of 16. Dynamic smem.
// ---------------------------------------------------------------------------
#define K2_SMEM_IN_BYTES   (16 * 10 * 68 * 4)           // 43520
#define K2_SMEM_W_OFF      43520
#define K2_SMEM_B_OFF      (43520 + 36864)              // 80384
#define K2_SMEM_PF_OFF     (K2_SMEM_B_OFF + 128)        // 80512
#define K2_SMEM_RED_OFF    (K2_SMEM_PF_OFF + 128)       // 80640
#define K2_SMEM_TOTAL      (K2_SMEM_RED_OFF + 32 * 129 * 4)  // 80640+16512 = 97152

template <int MODE>
__global__ __launch_bounds__(256) void k2_kernel(const float* __restrict__ pf_w,
                                                 const float* __restrict__ pf_b) {
    extern __shared__ char smem[];
    float*              s_in = (float*)smem;                         // [16][10][68]
    unsigned long long* s_w  = (unsigned long long*)(smem + K2_SMEM_W_OFF);   // [144][32]
    float*              s_b  = (float*)(smem + K2_SMEM_B_OFF);       // [32]
    float*              s_pf = (float*)(smem + K2_SMEM_PF_OFF);      // [32]
    float*              s_red = (float*)(smem + K2_SMEM_RED_OFF);    // [32][129] / score buf
    __shared__ int s_cnt;

    int tid = threadIdx.x;
    int b = blockIdx.z, bx = blockIdx.x, by = blockIdx.y;
    if (tid == 0) s_cnt = 0;

    for (int i = tid; i < 4608; i += 256) s_w[i] = g_w2p[i];
    if (tid < 32) {
        s_b[tid] = g_bias2[tid];
        if (MODE == 0) s_pf[tid] = pf_w[tid];
    }

    int y0 = by * 8 - 1, x0 = bx * 64 - 1;
    for (int i = tid; i < 10560; i += 256) {  // 16*10*66
        int cin = i / 660, rem = i % 660, r = rem / 66, c = rem % 66;
        int gy = y0 + r, gx = x0 + c;
        float v = 0.f;
        if ((unsigned)gy < 256u && (unsigned)gx < 256u)
            v = g_pool[((b * 16 + cin) * 256 + gy) * 256 + gx];
        s_in[cin * 680 + r * 68 + c] = v;
    }
    __syncthreads();

    int cog = tid >> 7, sp = tid & 127, ry = sp >> 4, xc = sp & 15;
    unsigned long long a0[16], a1[16];  // px pair (x,x+1) / (x+2,x+3), 16 channels
#pragma unroll
    for (int i = 0; i < 16; i++) { a0[i] = 0ull; a1[i] = 0ull; }

    for (int cin = 0; cin < 16; cin++) {
        float rw[3][6];
#pragma unroll
        for (int j = 0; j < 3; j++) {
            const float* p = s_in + cin * 680 + (ry + j) * 68 + xc * 4;
            float4 q = *(const float4*)p;
            float2 q2 = *(const float2*)(p + 4);
            rw[j][0] = q.x; rw[j][1] = q.y; rw[j][2] = q.z; rw[j][3] = q.w;
            rw[j][4] = q2.x; rw[j][5] = q2.y;
        }
#pragma unroll
        for (int ky = 0; ky < 3; ky++) {
#pragma unroll
            for (int kx = 0; kx < 3; kx++) {
                unsigned long long i0 = pk2(rw[ky][kx],     rw[ky][kx + 1]);
                unsigned long long i1 = pk2(rw[ky][kx + 2], rw[ky][kx + 3]);
                const ulonglong2* wv =
                    (const ulonglong2*)(s_w + (cin * 9 + ky * 3 + kx) * 32 + cog * 16);
#pragma unroll
                for (int c2 = 0; c2 < 8; c2++) {
                    ulonglong2 w = wv[c2];
                    a0[2 * c2]     = f2fma(i0, w.x, a0[2 * c2]);
                    a1[2 * c2]     = f2fma(i1, w.x, a1[2 * c2]);
                    a0[2 * c2 + 1] = f2fma(i0, w.y, a0[2 * c2 + 1]);
                    a1[2 * c2 + 1] = f2fma(i1, w.y, a1[2 * c2 + 1]);
                }
            }
        }
    }

    int y = by * 8 + ry, xg = bx * 64 + xc * 4;

    if (MODE == 0) {
        // proposal-filter score: dot over this thread's 16 channels
        float sc0 = 0.f, sc1 = 0.f, sc2 = 0.f, sc3 = 0.f;
#pragma unroll
        for (int co = 0; co < 16; co++) {
            float bb = s_b[cog * 16 + co], pw = s_pf[cog * 16 + co];
            float v0, v1, v2, v3;
            upk2(a0[co], v0, v1);
            upk2(a1[co], v2, v3);
            sc0 += fmaxf(v0 + bb, 0.f) * pw;
            sc1 += fmaxf(v1 + bb, 0.f) * pw;
            sc2 += fmaxf(v2 + bb, 0.f) * pw;
            sc3 += fmaxf(v3 + bb, 0.f) * pw;
        }
        if (cog == 1) {
            s_red[sp * 4 + 0] = sc0; s_red[sp * 4 + 1] = sc1;
            s_red[sp * 4 + 2] = sc2; s_red[sp * 4 + 3] = sc3;
        }
        __syncthreads();
        if (cog == 0) {
            float pb = pf_b[0];
            float t0 = sc0 + s_red[sp * 4 + 0] + pb;
            float t1 = sc1 + s_red[sp * 4 + 1] + pb;
            float t2 = sc2 + s_red[sp * 4 + 2] + pb;
            float t3 = sc3 + s_red[sp * 4 + 3] + pb;
            unsigned char m0 = t0 > 0.f, m1 = t1 > 0.f, m2 = t2 > 0.f, m3 = t3 > 0.f;
            unsigned char* mp = g_mask + y * 256 + xg;
            mp[0] = m0; mp[1] = m1; mp[2] = m2; mp[3] = m3;
            atomicAdd(&s_cnt, (int)(m0 + m1 + m2 + m3));
        }
        __syncthreads();
        if (tid == 0) atomicAdd(&g_count_i, s_cnt);
    } else {
        unsigned mm = *(const unsigned*)(g_mask + y * 256 + xg);
        float m0 = (float)(mm & 0xffu), m1 = (float)((mm >> 8) & 0xffu);
        float m2 = (float)((mm >> 16) & 0xffu), m3 = (float)(mm >> 24);
        float part[16];
#pragma unroll
        for (int co = 0; co < 16; co++) {
            float bb = s_b[cog * 16 + co];
            float v0, v1, v2, v3;
            upk2(a0[co], v0, v1);
            upk2(a1[co], v2, v3);
            part[co] = m0 * fmaxf(v0 + bb, 0.f) + m1 * fmaxf(v1 + bb, 0.f) +
                       m2 * fmaxf(v2 + bb, 0.f) + m3 * fmaxf(v3 + bb, 0.f);
        }
#pragma unroll
        for (int co = 0; co < 16; co++)
            s_red[(cog * 16 + co) * 129 + sp] = part[co];
        __syncthreads();
        if (tid < 32) {
            float s = 0.f;
            const float* p = s_red + tid * 129;
            for (int i = 0; i < 128; i++) s += p[i];
            atomicAdd(&g_S[b * 32 + tid], s);
        }
    }
}

// ---------------------------------------------------------------------------
// K3: head. cls_mean = (S/denom) @ vocab_w^T + vocab_b*(count/denom);
//     out = cls_mean @ cls_w^T + cls_b
// ---------------------------------------------------------------------------
__global__ void k3_kernel(const float* __restrict__ vw, const float* __restrict__ vb,
                          const float* __restrict__ cw, const float* __restrict__ cb,
                          float* __restrict__ out) {
    __shared__ float s_mean[512];   // [16][32]
    __shared__ float s_cm[1280];    // [16][80]
    int t = threadIdx.x;  // 256
    int cnt = g_count_i;
    float denom = (float)(cnt > 0 ? cnt : 1);
    float frac = cnt > 0 ? 1.f : 0.f;
    for (int i = t; i < 512; i += 256) s_mean[i] = g_S[i] / denom;
    __syncthreads();
    for (int i = t; i < 16 * 80; i += 256) {
        int b = i / 80, k = i % 80;
        float a = vb[k] * frac;
        const float* wm = vw + k * 32;
        const float* mm = s_mean + b * 32;
#pragma unroll
        for (int c = 0; c < 32; c++) a += mm[c] * wm[c];
        s_cm[i] = a;
    }
    __syncthreads();
    for (int i = t; i < 1280; i += 256) {
        int b = i / 80, j = i % 80;
        float a = cb[j];
        const float* w = cw + j * 80;
        const float* m = s_cm + b * 80;
#pragma unroll
        for (int k = 0; k < 80; k++) a += m[k] * w[k];
        out[i] = a;
    }
}

// ---------------------------------------------------------------------------
extern "C" void kernel_launch(void* const* d_in, const int* in_sizes, int n_in,
                              void* d_out, int out_size) {
    const float* x   = (const float*)d_in[0];
    const float* w1  = (const float*)d_in[1];
    const float* g1  = (const float*)d_in[2];
    const float* b1  = (const float*)d_in[3];
    const float* m1  = (const float*)d_in[4];
    const float* v1  = (const float*)d_in[5];
    const float* w2  = (const float*)d_in[6];
    const float* g2  = (const float*)d_in[7];
    const float* b2  = (const float*)d_in[8];
    const float* m2  = (const float*)d_in[9];
    const float* v2  = (const float*)d_in[10];
    const float* pfw = (const float*)d_in[11];
    const float* pfb = (const float*)d_in[12];
    const float* vw  = (const float*)d_in[13];
    const float* vb  = (const float*)d_in[14];
    const float* cw  = (const float*)d_in[15];
    const float* cb  = (const float*)d_in[16];
    float* out = (float*)d_out;

    cudaFuncSetAttribute(k2_kernel<0>, cudaFuncAttributeMaxDynamicSharedMemorySize,
                         K2_SMEM_TOTAL);
    cudaFuncSetAttribute(k2_kernel<1>, cudaFuncAttributeMaxDynamicSharedMemorySize,
                         K2_SMEM_TOTAL);

    prep_kernel<<<1, 256>>>(w1, g1, b1, m1, v1, w2, g2, b2, m2, v2);
    k1_kernel<<<dim3(16, 16, 16), 256>>>(x);
    k2_kernel<0><<<dim3(4, 32, 1), 256, K2_SMEM_TOTAL>>>(pfw, pfb);
    k2_kernel<1><<<dim3(4, 32, 16), 256, K2_SMEM_TOTAL>>>(pfw, pfb);
    k3_kernel<<<1, 256>>>(vw, vb, cw, cb, out);
}

// round 2
// speedup vs baseline: 1.0598x; 1.0598x over previous
#include <cuda_runtime.h>
#include <cuda_bf16.h>
#include <cstdint>

// ---------------------------------------------------------------------------
//   x        [16, 3, 512, 512]
//   conv1_w  [16, 3, 3, 3]   + bn1 (16)
//   conv2_w  [32, 16, 3, 3]  + bn2 (32)
//   pf_w[32], pf_b[1], vocab_w[80,32], vocab_b[80], cls_w[80,80], cls_b[80]
//   out      [16, 80] fp32
// ---------------------------------------------------------------------------

#define BN_EPS 1e-5f

__device__ float              g_pool[16 * 16 * 256 * 256];
__device__ unsigned char      g_mask[256 * 256];
__device__ int                g_count_i;
__device__ float              g_S[16 * 32];
__device__ unsigned long long g_w1p[27 * 16];    // folded conv1 w, packed {w,w}
__device__ unsigned long long g_w2p[144 * 32];   // folded conv2 w, packed {w,w}
__device__ float              g_bias1[16];
__device__ float              g_bias2[32];

// ---- f32x2 helpers --------------------------------------------------------
__device__ __forceinline__ unsigned long long pk2(float a, float b) {
    unsigned long long r;
    asm("mov.b64 %0, {%1, %2};" : "=l"(r) : "f"(a), "f"(b));
    return r;
}
__device__ __forceinline__ void upk2(unsigned long long v, float& a, float& b) {
    asm("mov.b64 {%0, %1}, %2;" : "=f"(a), "=f"(b) : "l"(v));
}
__device__ __forceinline__ unsigned long long f2fma(unsigned long long a,
                                                    unsigned long long b,
                                                    unsigned long long c) {
    unsigned long long d;
    asm("fma.rn.f32x2 %0, %1, %2, %3;" : "=l"(d) : "l"(a), "l"(b), "l"(c));
    return d;
}

// ---------------------------------------------------------------------------
__global__ void prep_kernel(const float* __restrict__ w1,
                            const float* __restrict__ g1, const float* __restrict__ b1,
                            const float* __restrict__ m1, const float* __restrict__ v1,
                            const float* __restrict__ w2,
                            const float* __restrict__ g2, const float* __restrict__ b2,
                            const float* __restrict__ m2, const float* __restrict__ v2) {
    int t = threadIdx.x;  // 256
    for (int i = t; i < 512; i += 256) g_S[i] = 0.f;
    if (t == 0) g_count_i = 0;
    for (int i = t; i < 16 * 27; i += 256) {
        int co = i / 27, k = i % 27;
        float s = g1[co] * rsqrtf(v1[co] + BN_EPS);
        float w = w1[co * 27 + k] * s;
        g_w1p[k * 16 + co] = pk2(w, w);
    }
    for (int i = t; i < 32 * 144; i += 256) {
        int co = i / 144, k = i % 144;
        float s = g2[co] * rsqrtf(v2[co] + BN_EPS);
        float w = w2[co * 144 + k] * s;
        g_w2p[k * 32 + co] = pk2(w, w);
    }
    if (t < 16) {
        float s = g1[t] * rsqrtf(v1[t] + BN_EPS);
        g_bias1[t] = b1[t] - m1[t] * s;
    }
    if (t < 32) {
        float s = g2[t] * rsqrtf(v2[t] + BN_EPS);
        g_bias2[t] = b2[t] - m2[t] * s;
    }
}

// ---------------------------------------------------------------------------
// K1: conv1(3->16) + BN + ReLU + maxpool2x2.
// 256 threads = 2 channel-groups(8ch) x 128 spatial; thread = 1 pooled px.
// Pooled tile 16x8 (conv tile 32x16). 3 CTAs/SM target.
// ---------------------------------------------------------------------------
__global__ __launch_bounds__(256, 3) void k1_kernel(const float* __restrict__ x) {
    __shared__ float              s_x[3 * 18 * 36];   // halo tile, row stride 36
    __shared__ unsigned long long s_w[27 * 16];
    __shared__ float              s_b[16];

    int b = blockIdx.z, bx = blockIdx.x, by = blockIdx.y;
    int tid = threadIdx.x;

    for (int i = tid; i < 27 * 16; i += 256) s_w[i] = g_w1p[i];
    if (tid < 16) s_b[tid] = g_bias1[tid];

    int y0 = by * 16 - 1, x0 = bx * 32 - 1;
    for (int i = tid; i < 3 * 18 * 34; i += 256) {
        int cin = i / 612, rem = i % 612, r = rem / 34, c = rem % 34;
        int gy = y0 + r, gx = x0 + c;
        float v = 0.f;
        if ((unsigned)gy < 512u && (unsigned)gx < 512u)
            v = x[((b * 3 + cin) * 512 + gy) * 512 + gx];
        s_x[cin * 648 + r * 36 + c] = v;
    }
    __syncthreads();

    int cog = tid >> 7, sp = tid & 127, tx = sp & 15, ty = sp >> 4;
    unsigned long long a0[8], a1[8];
#pragma unroll
    for (int i = 0; i < 8; i++) { a0[i] = 0ull; a1[i] = 0ull; }

#pragma unroll
    for (int cin = 0; cin < 3; cin++) {
        float rv[4][4];
        const float* base = s_x + cin * 648 + (2 * ty) * 36 + 2 * tx;
#pragma unroll
        for (int r = 0; r < 4; r++) {
            float2 q0 = *(const float2*)(base + r * 36);
            float2 q1 = *(const float2*)(base + r * 36 + 2);
            rv[r][0] = q0.x; rv[r][1] = q0.y; rv[r][2] = q1.x; rv[r][3] = q1.y;
        }
#pragma unroll
        for (int ky = 0; ky < 3; ky++) {
#pragma unroll
            for (int kx = 0; kx < 3; kx++) {
                unsigned long long i0 = pk2(rv[ky][kx],     rv[ky][kx + 1]);
                unsigned long long i1 = pk2(rv[ky + 1][kx], rv[ky + 1][kx + 1]);
                const ulonglong2* wv =
                    (const ulonglong2*)(s_w + (cin * 9 + ky * 3 + kx) * 16 + cog * 8);
#pragma unroll
                for (int c2 = 0; c2 < 4; c2++) {
                    ulonglong2 w = wv[c2];
                    a0[2 * c2]     = f2fma(i0, w.x, a0[2 * c2]);
                    a1[2 * c2]     = f2fma(i1, w.x, a1[2 * c2]);
                    a0[2 * c2 + 1] = f2fma(i0, w.y, a0[2 * c2 + 1]);
                    a1[2 * c2 + 1] = f2fma(i1, w.y, a1[2 * c2 + 1]);
                }
            }
        }
    }

    int py = by * 8 + ty, px = bx * 16 + tx;
#pragma unroll
    for (int co = 0; co < 8; co++) {
        float p0, p1, p2, p3;
        upk2(a0[co], p0, p1);
        upk2(a1[co], p2, p3);
        float m = fmaxf(fmaxf(p0, p1), fmaxf(p2, p3)) + s_b[cog * 8 + co];
        m = fmaxf(m, 0.f);
        g_pool[((b * 16 + cog * 8 + co) * 256 + py) * 256 + px] = m;
    }
}

// ---------------------------------------------------------------------------
// K2: conv2(16->32) + BN + ReLU, feature map never materialized.
// 256 threads = 4 channel-groups(8ch) x 64 spatial; thread = 4 px (2 f32x2
// pairs). Tile 32x8. Dynamic smem ~63KB -> 3 CTAs/SM.
// MODE 0: batch 0 -> proposal mask + count.  MODE 1: masked channel sums.
// ---------------------------------------------------------------------------
#define K2_IN_BYTES   (16 * 10 * 36 * 4)              // 23040
#define K2_W_OFF      K2_IN_BYTES                      // 23040
#define K2_B_OFF      (K2_W_OFF + 144 * 32 * 8)        // 59904
#define K2_PF_OFF     (K2_B_OFF + 128)                 // 60032
#define K2_SC_OFF     (K2_PF_OFF + 128)                // 60160
#define K2_SMEM_TOTAL (K2_SC_OFF + 3 * 256 * 4)        // 63232

template <int MODE>
__global__ __launch_bounds__(256, 3) void k2_kernel(const float* __restrict__ pf_w,
                                                    const float* __restrict__ pf_b) {
    extern __shared__ char smem[];
    float*              s_in = (float*)smem;                          // [16][10][36]
    unsigned long long* s_w  = (unsigned long long*)(smem + K2_W_OFF);// [144][32]
    float*              s_b  = (float*)(smem + K2_B_OFF);
    float*              s_pf = (float*)(smem + K2_PF_OFF);
    float*              s_sc = (float*)(smem + K2_SC_OFF);            // [3][256]

    int tid = threadIdx.x;
    int b = blockIdx.z, bx = blockIdx.x, by = blockIdx.y;

    for (int i = tid; i < 4608; i += 256) s_w[i] = g_w2p[i];
    if (tid < 32) {
        s_b[tid] = g_bias2[tid];
        if (MODE == 0) s_pf[tid] = pf_w[tid];
    }

    int y0 = by * 8 - 1, x0 = bx * 32 - 1;
    for (int i = tid; i < 5440; i += 256) {  // 16*10*34
        int cin = i / 340, rem = i % 340, r = rem / 34, c = rem % 34;
        int gy = y0 + r, gx = x0 + c;
        float v = 0.f;
        if ((unsigned)gy < 256u && (unsigned)gx < 256u)
            v = g_pool[((b * 16 + cin) * 256 + gy) * 256 + gx];
        s_in[cin * 360 + r * 36 + c] = v;
    }
    __syncthreads();

    int cog = tid >> 6, sp = tid & 63, ry = sp >> 3, xc = sp & 7;
    unsigned long long a0[8], a1[8];
#pragma unroll
    for (int i = 0; i < 8; i++) { a0[i] = 0ull; a1[i] = 0ull; }

#pragma unroll 4
    for (int cin = 0; cin < 16; cin++) {
        float rw[3][6];
#pragma unroll
        for (int j = 0; j < 3; j++) {
            const float* p = s_in + cin * 360 + (ry + j) * 36 + xc * 4;
            float4 q = *(const float4*)p;
            float2 q2 = *(const float2*)(p + 4);
            rw[j][0] = q.x; rw[j][1] = q.y; rw[j][2] = q.z; rw[j][3] = q.w;
            rw[j][4] = q2.x; rw[j][5] = q2.y;
        }
#pragma unroll
        for (int ky = 0; ky < 3; ky++) {
#pragma unroll
            for (int kx = 0; kx < 3; kx++) {
                unsigned long long i0 = pk2(rw[ky][kx],     rw[ky][kx + 1]);
                unsigned long long i1 = pk2(rw[ky][kx + 2], rw[ky][kx + 3]);
                const ulonglong2* wv =
                    (const ulonglong2*)(s_w + (cin * 9 + ky * 3 + kx) * 32 + cog * 8);
#pragma unroll
                for (int c2 = 0; c2 < 4; c2++) {
                    ulonglong2 w = wv[c2];
                    a0[2 * c2]     = f2fma(i0, w.x, a0[2 * c2]);
                    a1[2 * c2]     = f2fma(i1, w.x, a1[2 * c2]);
                    a0[2 * c2 + 1] = f2fma(i0, w.y, a0[2 * c2 + 1]);
                    a1[2 * c2 + 1] = f2fma(i1, w.y, a1[2 * c2 + 1]);
                }
            }
        }
    }

    int y = by * 8 + ry, xg = bx * 32 + xc * 4;

    if (MODE == 0) {
        float sc0 = 0.f, sc1 = 0.f, sc2 = 0.f, sc3 = 0.f;
#pragma unroll
        for (int co = 0; co < 8; co++) {
            float bb = s_b[cog * 8 + co], pw = s_pf[cog * 8 + co];
            float v0, v1, v2, v3;
            upk2(a0[co], v0, v1);
            upk2(a1[co], v2, v3);
            sc0 += fmaxf(v0 + bb, 0.f) * pw;
            sc1 += fmaxf(v1 + bb, 0.f) * pw;
            sc2 += fmaxf(v2 + bb, 0.f) * pw;
            sc3 += fmaxf(v3 + bb, 0.f) * pw;
        }
        if (cog > 0) {
            float* d = s_sc + (cog - 1) * 256 + sp * 4;
            d[0] = sc0; d[1] = sc1; d[2] = sc2; d[3] = sc3;
        }
        __syncthreads();
        if (cog == 0) {
            float pb = pf_b[0];
            float t0 = sc0 + pb, t1 = sc1 + pb, t2 = sc2 + pb, t3 = sc3 + pb;
#pragma unroll
            for (int g = 0; g < 3; g++) {
                const float* s = s_sc + g * 256 + sp * 4;
                t0 += s[0]; t1 += s[1]; t2 += s[2]; t3 += s[3];
            }
            uchar4 mv;
            mv.x = t0 > 0.f; mv.y = t1 > 0.f; mv.z = t2 > 0.f; mv.w = t3 > 0.f;
            *(uchar4*)(g_mask + y * 256 + xg) = mv;
            int c = (int)mv.x + mv.y + mv.z + mv.w;
            c = __reduce_add_sync(0xffffffffu, c);
            if ((tid & 31) == 0) atomicAdd(&g_count_i, c);
        }
    } else {
        unsigned mm = *(const unsigned*)(g_mask + y * 256 + xg);
        float m0 = (float)(mm & 0xffu), m1 = (float)((mm >> 8) & 0xffu);
        float m2 = (float)((mm >> 16) & 0xffu), m3 = (float)(mm >> 24);
#pragma unroll
        for (int co = 0; co < 8; co++) {
            float bb = s_b[cog * 8 + co];
            float v0, v1, v2, v3;
            upk2(a0[co], v0, v1);
            upk2(a1[co], v2, v3);
            float part = m0 * fmaxf(v0 + bb, 0.f) + m1 * fmaxf(v1 + bb, 0.f) +
                         m2 * fmaxf(v2 + bb, 0.f) + m3 * fmaxf(v3 + bb, 0.f);
#pragma unroll
            for (int off = 16; off > 0; off >>= 1)
                part += __shfl_xor_sync(0xffffffffu, part, off);
            if ((tid & 31) == 0)
                atomicAdd(&g_S[b * 32 + cog * 8 + co], part);
        }
    }
}

// ---------------------------------------------------------------------------
__global__ void k3_kernel(const float* __restrict__ vw, const float* __restrict__ vb,
                          const float* __restrict__ cw, const float* __restrict__ cb,
                          float* __restrict__ out) {
    __shared__ float s_mean[512];
    __shared__ float s_cm[1280];
    int t = threadIdx.x;  // 256
    int cnt = g_count_i;
    float denom = (float)(cnt > 0 ? cnt : 1);
    float frac = cnt > 0 ? 1.f : 0.f;
    for (int i = t; i < 512; i += 256) s_mean[i] = g_S[i] / denom;
    __syncthreads();
    for (int i = t; i < 16 * 80; i += 256) {
        int b = i / 80, k = i % 80;
        float a = vb[k] * frac;
        const float* wm = vw + k * 32;
        const float* mm = s_mean + b * 32;
#pragma unroll
        for (int c = 0; c < 32; c++) a += mm[c] * wm[c];
        s_cm[i] = a;
    }
    __syncthreads();
    for (int i = t; i < 1280; i += 256) {
        int b = i / 80, j = i % 80;
        float a = cb[j];
        const float* w = cw + j * 80;
        const float* m = s_cm + b * 80;
#pragma unroll
        for (int k = 0; k < 80; k++) a += m[k] * w[k];
        out[i] = a;
    }
}

// ---------------------------------------------------------------------------
extern "C" void kernel_launch(void* const* d_in, const int* in_sizes, int n_in,
                              void* d_out, int out_size) {
    const float* x   = (const float*)d_in[0];
    const float* w1  = (const float*)d_in[1];
    const float* g1  = (const float*)d_in[2];
    const float* b1  = (const float*)d_in[3];
    const float* m1  = (const float*)d_in[4];
    const float* v1  = (const float*)d_in[5];
    const float* w2  = (const float*)d_in[6];
    const float* g2  = (const float*)d_in[7];
    const float* b2  = (const float*)d_in[8];
    const float* m2  = (const float*)d_in[9];
    const float* v2  = (const float*)d_in[10];
    const float* pfw = (const float*)d_in[11];
    const float* pfb = (const float*)d_in[12];
    const float* vw  = (const float*)d_in[13];
    const float* vb  = (const float*)d_in[14];
    const float* cw  = (const float*)d_in[15];
    const float* cb  = (const float*)d_in[16];
    float* out = (float*)d_out;

    cudaFuncSetAttribute(k2_kernel<0>, cudaFuncAttributeMaxDynamicSharedMemorySize,
                         K2_SMEM_TOTAL);
    cudaFuncSetAttribute(k2_kernel<1>, cudaFuncAttributeMaxDynamicSharedMemorySize,
                         K2_SMEM_TOTAL);

    prep_kernel<<<1, 256>>>(w1, g1, b1, m1, v1, w2, g2, b2, m2, v2);
    k1_kernel<<<dim3(16, 32, 16), 256>>>(x);
    k2_kernel<0><<<dim3(8, 32, 1), 256, K2_SMEM_TOTAL>>>(pfw, pfb);
    k2_kernel<1><<<dim3(8, 32, 16), 256, K2_SMEM_TOTAL>>>(pfw, pfb);
    k3_kernel<<<1, 256>>>(vw, vb, cw, cb, out);
}